// round 16
// baseline (speedup 1.0000x reference)
#include <cuda_runtime.h>
#include <cuda_fp16.h>
#include <cstdint>

#define BB 4
#define CIN 64
#define HH 128
#define WW 128
#define HID 384
#define COUT 64
#define NPATCH 256          // 16 x 16
#define NP 52608            // params per patch
#define P2OFF 24576         // K2 offset (hidden*Cin)
#define P3OFF 28032         // W3 offset (+hidden*9)
#define EPSV 1e-5f

// scratch (static __device__ arrays; no runtime allocation)
__device__ __half g_wth[(size_t)BB * NPATCH * NP];         // fp16 transposed weights ~107MB
__device__ __half g_h1[(size_t)BB * HID * HH * WW];        // image layout, fp16 ~50MB
__device__ __half g_h2[(size_t)BB * NPATCH * HID * 64];    // patch-major [ch][px], fp16 ~50MB

// ---- cp.async helpers
__device__ __forceinline__ void cp16(uint32_t dst_smem, const void* src) {
    asm volatile("cp.async.cg.shared.global [%0], [%1], 16;"
                 :: "r"(dst_smem), "l"(src) : "memory");
}
#define CP_COMMIT() asm volatile("cp.async.commit_group;" ::: "memory")
#define CP_WAIT0()  asm volatile("cp.async.wait_group 0;" ::: "memory")

// ---- mma / ldmatrix helpers (arch-agnostic PTX, works on compute_103)
__device__ __forceinline__ void ldsm4(uint32_t* r, uint32_t addr) {
    asm volatile("ldmatrix.sync.aligned.m8n8.x4.shared.b16 {%0,%1,%2,%3}, [%4];"
                 : "=r"(r[0]), "=r"(r[1]), "=r"(r[2]), "=r"(r[3]) : "r"(addr));
}
__device__ __forceinline__ void ldsm4t(uint32_t* r, uint32_t addr) {
    asm volatile("ldmatrix.sync.aligned.m8n8.x4.trans.shared.b16 {%0,%1,%2,%3}, [%4];"
                 : "=r"(r[0]), "=r"(r[1]), "=r"(r[2]), "=r"(r[3]) : "r"(addr));
}
__device__ __forceinline__ void mma16816(float* d, const uint32_t* a, const uint32_t* b) {
    asm volatile("mma.sync.aligned.m16n8k16.row.col.f32.f16.f16.f32 "
                 "{%0,%1,%2,%3}, {%4,%5,%6,%7}, {%8,%9}, {%0,%1,%2,%3};"
                 : "+f"(d[0]), "+f"(d[1]), "+f"(d[2]), "+f"(d[3])
                 : "r"(a[0]), "r"(a[1]), "r"(a[2]), "r"(a[3]), "r"(b[0]), "r"(b[1]));
}
__device__ __forceinline__ float relu6f(float v) { return fminf(fmaxf(v, 0.f), 6.f); }

// ---------------------------------------------------------------------------
// Transpose w [B][NP][256(fg)] -> g_wth [B][256(fg)][NP]  fp16
// Tile 128 params x 32 fg; float4 reads (MLP 4), uint4 fp16 writes.
// p0 offset comes from blockIdx.y + poff (allows range splitting).
// ---------------------------------------------------------------------------
__global__ __launch_bounds__(256) void k_transpose(const float* __restrict__ w, int poff) {
    __shared__ float tile[128][33];
    int b = blockIdx.z;
    int g0 = blockIdx.x * 32;
    int p0 = poff + blockIdx.y * 128;
    size_t base = (size_t)b * NP * 256;
    int tid = threadIdx.x;

    #pragma unroll
    for (int t = 0; t < 4; t++) {
        int idx = tid + t * 256;            // 0..1023
        int row = idx >> 3, c4 = (idx & 7) * 4;
        float4 v = *(const float4*)&w[base + (size_t)(p0 + row) * 256 + g0 + c4];
        tile[row][c4]     = v.x;
        tile[row][c4 + 1] = v.y;
        tile[row][c4 + 2] = v.z;
        tile[row][c4 + 3] = v.w;
    }
    __syncthreads();
    #pragma unroll
    for (int t = 0; t < 2; t++) {
        int idx = tid + t * 256;            // 0..511
        int g = idx >> 4, c16 = (idx & 15) * 8;
        __half2 h[4];
        #pragma unroll
        for (int e = 0; e < 4; e++)
            h[e] = __floats2half2_rn(tile[c16 + e * 2][g], tile[c16 + e * 2 + 1][g]);
        uint4 ov = make_uint4(*(uint32_t*)&h[0], *(uint32_t*)&h[1],
                              *(uint32_t*)&h[2], *(uint32_t*)&h[3]);
        *(uint4*)&g_wth[((size_t)b * 256 + g0 + g) * NP + p0 + c16] = ov;
    }
}

// ---------------------------------------------------------------------------
// Stage 1 (HMMA): 2 patches/CTA, 128 threads (4 warps; warp owns 32 px).
// ---------------------------------------------------------------------------
#define HR1 136                          // halves per xs row
#define XS1B (64 * HR1 * 2)              // 17408 bytes
#define RS1 72                           // halves per ws row
#define WS1B (2 * 64 * RS1 * 2)          // 18432 bytes per buffer
__global__ __launch_bounds__(128, 4) void k_stage1(
    const float* __restrict__ x,
    const float* __restrict__ g1, const float* __restrict__ b1,
    const float* __restrict__ m1, const float* __restrict__ v1)
{
    extern __shared__ char sm[];
    uint32_t smem_u32 = (uint32_t)__cvta_generic_to_shared(sm);
    uint32_t xs_u32 = smem_u32;
    uint32_t ws_u32 = smem_u32 + XS1B;

    int blk = blockIdx.x;             // 0..511
    int b = blk >> 7, pp = blk & 127;
    int pid0 = pp * 2, pid1 = pp * 2 + 1;
    int f = pid0 >> 4, gg0 = pid0 & 15;
    int y0 = f * 8, x0 = gg0 * 8;
    int tid = threadIdx.x;
    int warp = tid >> 5, lane = tid & 31;
    int lr = lane & 7, lm = (lane >> 3) & 1, lk = lane >> 4;
    int patch_l = warp >> 1;
    int wb = warp * 32;               // xs column base

    const __half* Wb0 = g_wth + (size_t)(b * NPATCH + pid0) * NP;
    const __half* Wb1 = g_wth + (size_t)(b * NPATCH + pid1) * NP;

    auto fill_ws = [&](int ot, int bsel) {
        #pragma unroll
        for (int t = 0; t < 8; t++) {
            int idx = tid + t * 128;          // 0..1023
            int p = idx >> 9, o = (idx >> 3) & 63, c16 = idx & 7;
            const __half* src = (p ? Wb1 : Wb0) + (ot * 64 + o) * 64 + c16 * 8;
            cp16(ws_u32 + (uint32_t)(bsel * WS1B) +
                 (uint32_t)(p * 64 * RS1 + o * RS1 + c16 * 8) * 2, src);
        }
        CP_COMMIT();
    };

    fill_ws(0, 0);

    // load x (fp32) -> xs fp16 [c][128 px cols]
    for (int idx = tid; idx < 2048; idx += 128) {
        int c = idx >> 5, v = idx & 31;
        int pt = v >> 4, w4 = v & 15;
        int prow = w4 >> 1, q4 = (w4 & 1) * 4;
        float4 xv = *(const float4*)&x[(((size_t)b * CIN + c) * HH + y0 + prow) * WW
                                       + x0 + pt * 8 + q4];
        __half2 h01 = __floats2half2_rn(xv.x, xv.y);
        __half2 h23 = __floats2half2_rn(xv.z, xv.w);
        uint2 pk = make_uint2(*(uint32_t*)&h01, *(uint32_t*)&h23);
        int off = c * HR1 + pt * 64 + prow * 8 + q4;
        *(uint2*)(sm + off * 2) = pk;
    }

    int bb = 0;
    for (int ot = 0; ot < 6; ot++) {
        CP_WAIT0();
        __syncthreads();
        if (ot < 5) fill_ws(ot + 1, bb ^ 1);

        float acc[4][4][4];
        #pragma unroll
        for (int m = 0; m < 4; m++)
            #pragma unroll
            for (int n = 0; n < 4; n++)
                #pragma unroll
                for (int e = 0; e < 4; e++) acc[m][n][e] = 0.f;

        uint32_t wpb = ws_u32 + (uint32_t)(bb * WS1B) + (uint32_t)(patch_l * 64 * RS1) * 2;
        #pragma unroll
        for (int k0 = 0; k0 < 64; k0 += 16) {
            uint32_t a[4][4];
            #pragma unroll
            for (int m = 0; m < 4; m++)
                ldsm4(a[m], wpb + (uint32_t)((m * 16 + lr + lm * 8) * RS1 + k0 + lk * 8) * 2);
            uint32_t bf[2][4];
            #pragma unroll
            for (int h = 0; h < 2; h++)
                ldsm4t(bf[h], xs_u32 + (uint32_t)((k0 + lr + lm * 8) * HR1 + wb + h * 16 + lk * 8) * 2);
            #pragma unroll
            for (int m = 0; m < 4; m++)
                #pragma unroll
                for (int n = 0; n < 4; n++)
                    mma16816(acc[m][n], a[m], &bf[n >> 1][(n & 1) * 2]);
        }

        // epilogue: bn1 + relu6 -> fp16 h1
        int q = (lane & 3) * 2;
        #pragma unroll
        for (int m = 0; m < 4; m++) {
            int o0 = ot * 64 + m * 16 + (lane >> 2);
            int o1 = o0 + 8;
            float inv0 = g1[o0] * rsqrtf(v1[o0] + EPSV);
            float sh0  = b1[o0] - m1[o0] * inv0;
            float inv1 = g1[o1] * rsqrtf(v1[o1] + EPSV);
            float sh1  = b1[o1] - m1[o1] * inv1;
            #pragma unroll
            for (int n = 0; n < 4; n++) {
                int p = (warp & 1) * 4 + n;
                size_t col = (size_t)x0 + patch_l * 8 + q;
                __half2 v0 = __floats2half2_rn(relu6f(acc[m][n][0] * inv0 + sh0),
                                               relu6f(acc[m][n][1] * inv0 + sh0));
                __half2 v1h = __floats2half2_rn(relu6f(acc[m][n][2] * inv1 + sh1),
                                                relu6f(acc[m][n][3] * inv1 + sh1));
                *(__half2*)&g_h1[(((size_t)b * HID + o0) * HH + y0 + p) * WW + col] = v0;
                *(__half2*)&g_h1[(((size_t)b * HID + o1) * HH + y0 + p) * WW + col] = v1h;
            }
        }
        bb ^= 1;
    }
}

// ---------------------------------------------------------------------------
// Stage 2 (vectorized rows): CTA = (b, f-row, 16-ch group).
// ---------------------------------------------------------------------------
#define S2_HROW 136                         // halves per hs row
#define S2_HSB  (16 * 10 * S2_HROW * 2)     // 43520 bytes
#define S2_KSB  (16 * 144 * 2)              // 4608 bytes
#define S2_SMEM (S2_HSB + S2_KSB)           // 48128 bytes
__global__ __launch_bounds__(128, 4) void k_stage2(
    const float* __restrict__ g2, const float* __restrict__ b2,
    const float* __restrict__ m2, const float* __restrict__ v2)
{
    extern __shared__ char sm2[];
    __half* hs = (__half*)sm2;              // [16 cl][10 ry][136]
    __half* ks = (__half*)(sm2 + S2_HSB);   // [16 patch][144]
    int bf = blockIdx.x;                    // b*16 + f
    int b = bf >> 4, f = bf & 15;
    int ch0 = blockIdx.y * 16;
    int tid = threadIdx.x;
    int y0 = f * 8;

    for (int idx = tid; idx < 2560; idx += 128) {
        int cl = idx / 160;
        int rem = idx - cl * 160;
        int ry = rem >> 4, c16 = rem & 15;
        int yy = y0 + ry - 1;
        yy = yy < 0 ? -yy : (yy >= HH ? 2 * HH - 2 - yy : yy);
        uint4 raw = *(const uint4*)&g_h1[(((size_t)b * HID + ch0 + cl) * HH + yy) * WW + c16 * 8];
        *(uint4*)&hs[cl * 1360 + ry * S2_HROW + c16 * 8] = raw;
    }
    for (int idx = tid; idx < 288; idx += 128) {
        int g = idx / 18, u = idx - (idx / 18) * 18;
        const __half* src = g_wth + (size_t)(b * NPATCH + f * 16 + g) * NP
                            + P2OFF + ch0 * 9 + u * 8;
        *(uint4*)&ks[g * 144 + u * 8] = *(const uint4*)src;
    }
    __syncthreads();

    int cl = tid >> 3, p = tid & 7;
    int ch = ch0 + cl;
    float inv = g2[ch] * rsqrtf(v2[ch] + EPSV);
    float sh  = b2[ch] - m2[ch] * inv;
    const __half* hrow = hs + cl * 1360 + p * S2_HROW;

    float cur[3][8], nxt[3][8], pl[3];
    #pragma unroll
    for (int r = 0; r < 3; r++) {
        uint4 raw = *(const uint4*)(hrow + r * S2_HROW);
        __half2* hp = (__half2*)&raw;
        #pragma unroll
        for (int e = 0; e < 4; e++) {
            float2 fv = __half22float2(hp[e]);
            cur[r][e * 2] = fv.x; cur[r][e * 2 + 1] = fv.y;
        }
    }
    #pragma unroll
    for (int r = 0; r < 3; r++) pl[r] = cur[r][1];

    for (int g = 0; g < 16; g++) {
        float nx0[3];
        if (g < 15) {
            #pragma unroll
            for (int r = 0; r < 3; r++) {
                uint4 raw = *(const uint4*)(hrow + r * S2_HROW + (g + 1) * 8);
                __half2* hp = (__half2*)&raw;
                #pragma unroll
                for (int e = 0; e < 4; e++) {
                    float2 fv = __half22float2(hp[e]);
                    nxt[r][e * 2] = fv.x; nxt[r][e * 2 + 1] = fv.y;
                }
            }
            #pragma unroll
            for (int r = 0; r < 3; r++) nx0[r] = nxt[r][0];
        } else {
            #pragma unroll
            for (int r = 0; r < 3; r++) nx0[r] = cur[r][6];
        }

        float kv[9];
        #pragma unroll
        for (int t = 0; t < 9; t++)
            kv[t] = __half2float(ks[g * 144 + cl * 9 + t]);

        float res[8];
        #pragma unroll
        for (int q = 0; q < 8; q++) {
            float a = 0.f;
            #pragma unroll
            for (int r = 0; r < 3; r++) {
                float wl = (q == 0) ? pl[r] : cur[r][q - 1];
                float wc = cur[r][q];
                float wr = (q == 7) ? nx0[r] : cur[r][q + 1];
                a += wl * kv[r * 3] + wc * kv[r * 3 + 1] + wr * kv[r * 3 + 2];
            }
            res[q] = relu6f(a * inv + sh);
        }

        __half2 q0 = __floats2half2_rn(res[0], res[1]);
        __half2 q1 = __floats2half2_rn(res[2], res[3]);
        __half2 q2 = __floats2half2_rn(res[4], res[5]);
        __half2 q3 = __floats2half2_rn(res[6], res[7]);
        uint4 ov = make_uint4(*(uint32_t*)&q0, *(uint32_t*)&q1,
                              *(uint32_t*)&q2, *(uint32_t*)&q3);
        int pid = f * 16 + g;
        *(uint4*)&g_h2[((size_t)(b * NPATCH + pid) * HID + ch) * 64 + p * 8] = ov;

        if (g < 15) {
            #pragma unroll
            for (int r = 0; r < 3; r++) {
                pl[r] = cur[r][7];
                #pragma unroll
                for (int e = 0; e < 8; e++) cur[r][e] = nxt[r][e];
            }
        }
    }
}

// ---------------------------------------------------------------------------
// Stage 3 (HMMA): 2 patches/CTA, K=384 in chunks of 32, cp.async dbl-buffered.
// ---------------------------------------------------------------------------
#define HR3 136                            // halves per hs row
#define HS3B (32 * HR3 * 2)                // 8704 bytes
#define RS3 40                             // halves per ws row
#define WS3B (2 * 64 * RS3 * 2)            // 10240 bytes
#define BUF3 (HS3B + WS3B)                 // 18944 bytes per buffer
__global__ __launch_bounds__(128, 4) void k_stage3(
    const float* __restrict__ x,
    const float* __restrict__ g3, const float* __restrict__ b3,
    const float* __restrict__ m3, const float* __restrict__ v3,
    float* __restrict__ out)
{
    extern __shared__ char sm[];
    uint32_t smem_u32 = (uint32_t)__cvta_generic_to_shared(sm);

    int blk = blockIdx.x;             // 0..511
    int b = blk >> 7, pp = blk & 127;
    int pid0 = pp * 2, pid1 = pp * 2 + 1;
    int f = pid0 >> 4, gg0 = pid0 & 15;
    int y0 = f * 8, x0 = gg0 * 8;
    int tid = threadIdx.x;
    int warp = tid >> 5, lane = tid & 31;
    int lr = lane & 7, lm = (lane >> 3) & 1, lk = lane >> 4;
    int patch_l = warp >> 1;
    int wb = warp * 32;

    const __half* Wb0 = g_wth + (size_t)(b * NPATCH + pid0) * NP + P3OFF;
    const __half* Wb1 = g_wth + (size_t)(b * NPATCH + pid1) * NP + P3OFF;
    const __half* Hb0 = g_h2 + (size_t)(b * NPATCH + pid0) * HID * 64;
    const __half* Hb1 = g_h2 + (size_t)(b * NPATCH + pid1) * HID * 64;

    auto fill3 = [&](int kt, int bsel) {
        uint32_t base = smem_u32 + (uint32_t)(bsel * BUF3);
        #pragma unroll
        for (int t = 0; t < 4; t++) {           // hs: 32k x 128px
            int idx = tid + t * 128;
            int k = idx >> 4, rem = idx & 15;
            int pt = rem >> 3, w8 = rem & 7;
            const __half* src = (pt ? Hb1 : Hb0) + (kt * 32 + k) * 64 + w8 * 8;
            cp16(base + (uint32_t)(k * HR3 + pt * 64 + w8 * 8) * 2, src);
        }
        #pragma unroll
        for (int t = 0; t < 4; t++) {           // ws: 2p x 64co x 32k
            int idx = tid + t * 128;
            int p = idx >> 8, rem = idx & 255;
            int co = rem >> 2, c16 = rem & 3;
            const __half* src = (p ? Wb1 : Wb0) + co * HID + kt * 32 + c16 * 8;
            cp16(base + HS3B + (uint32_t)(p * 64 * RS3 + co * RS3 + c16 * 8) * 2, src);
        }
        CP_COMMIT();
    };

    fill3(0, 0);

    float acc[4][4][4];
    #pragma unroll
    for (int m = 0; m < 4; m++)
        #pragma unroll
        for (int n = 0; n < 4; n++)
            #pragma unroll
            for (int e = 0; e < 4; e++) acc[m][n][e] = 0.f;

    int bb = 0;
    for (int kt = 0; kt < 12; kt++) {
        CP_WAIT0();
        __syncthreads();
        if (kt < 11) fill3(kt + 1, bb ^ 1);

        uint32_t hsb = smem_u32 + (uint32_t)(bb * BUF3);
        uint32_t wpb = hsb + HS3B + (uint32_t)(patch_l * 64 * RS3) * 2;
        #pragma unroll
        for (int k0 = 0; k0 < 32; k0 += 16) {
            uint32_t a[4][4];
            #pragma unroll
            for (int m = 0; m < 4; m++)
                ldsm4(a[m], wpb + (uint32_t)((m * 16 + lr + lm * 8) * RS3 + k0 + lk * 8) * 2);
            uint32_t bf[2][4];
            #pragma unroll
            for (int h = 0; h < 2; h++)
                ldsm4t(bf[h], hsb + (uint32_t)((k0 + lr + lm * 8) * HR3 + wb + h * 16 + lk * 8) * 2);
            #pragma unroll
            for (int m = 0; m < 4; m++)
                #pragma unroll
                for (int n = 0; n < 4; n++)
                    mma16816(acc[m][n], a[m], &bf[n >> 1][(n & 1) * 2]);
        }
        bb ^= 1;
    }

    // epilogue: out = x + bn3(acc)
    int q = (lane & 3) * 2;
    #pragma unroll
    for (int m = 0; m < 4; m++) {
        int co0 = m * 16 + (lane >> 2);
        int co1 = co0 + 8;
        float inv0 = g3[co0] * rsqrtf(v3[co0] + EPSV);
        float sh0  = b3[co0] - m3[co0] * inv0;
        float inv1 = g3[co1] * rsqrtf(v3[co1] + EPSV);
        float sh1  = b3[co1] - m3[co1] * inv1;
        #pragma unroll
        for (int n = 0; n < 4; n++) {
            int p = (warp & 1) * 4 + n;
            size_t col = (size_t)x0 + patch_l * 8 + q;
            size_t a0 = (((size_t)b * COUT + co0) * HH + y0 + p) * WW + col;
            size_t a1 = (((size_t)b * COUT + co1) * HH + y0 + p) * WW + col;
            float2 xr0 = *(const float2*)&x[a0];
            float2 xr1 = *(const float2*)&x[a1];
            float2 o0 = make_float2(xr0.x + (acc[m][n][0] * inv0 + sh0),
                                    xr0.y + (acc[m][n][1] * inv0 + sh0));
            float2 o1 = make_float2(xr1.x + (acc[m][n][2] * inv1 + sh1),
                                    xr1.y + (acc[m][n][3] * inv1 + sh1));
            *(float2*)&out[a0] = o0;
            *(float2*)&out[a1] = o1;
        }
    }
}

// ---------------------------------------------------------------------------
extern "C" void kernel_launch(void* const* d_in, const int* in_sizes, int n_in,
                              void* d_out, int out_size) {
    const float* x  = (const float*)d_in[0];
    const float* w  = (const float*)d_in[1];
    const float* g1 = (const float*)d_in[2];
    const float* b1 = (const float*)d_in[3];
    const float* m1 = (const float*)d_in[4];
    const float* v1 = (const float*)d_in[5];
    const float* g2 = (const float*)d_in[6];
    const float* b2 = (const float*)d_in[7];
    const float* m2 = (const float*)d_in[8];
    const float* v2 = (const float*)d_in[9];
    const float* g3 = (const float*)d_in[10];
    const float* b3 = (const float*)d_in[11];
    const float* m3 = (const float*)d_in[12];
    const float* v3 = (const float*)d_in[13];
    float* out = (float*)d_out;

    const int S1_SMEM = XS1B + 2 * WS1B;   // 54272
    const int S3_SMEM = 2 * BUF3;          // 37888

    static bool init = false;
    static cudaStream_t s2;
    static cudaEvent_t ev_fork, ev_join;
    if (!init) {
        cudaFuncSetAttribute(k_stage1, cudaFuncAttributeMaxDynamicSharedMemorySize, S1_SMEM);
        cudaFuncSetAttribute(k_stage2, cudaFuncAttributeMaxDynamicSharedMemorySize, S2_SMEM);
        cudaFuncSetAttribute(k_stage3, cudaFuncAttributeMaxDynamicSharedMemorySize, S3_SMEM);
        cudaStreamCreateWithFlags(&s2, cudaStreamNonBlocking);
        cudaEventCreateWithFlags(&ev_fork, cudaEventDisableTiming);
        cudaEventCreateWithFlags(&ev_join, cudaEventDisableTiming);
        init = true;
    }

    // Fork: T_rest (K2+W3 transpose) runs on s2, overlapping T_W1 + stage1.
    cudaEventRecord(ev_fork, 0);
    cudaStreamWaitEvent(s2, ev_fork, 0);
    k_transpose<<<dim3(8, (NP - P2OFF) / 128, BB), 256, 0, s2>>>(w, P2OFF);  // 219 tiles
    cudaEventRecord(ev_join, s2);

    // Main stream: T_W1 -> stage1
    k_transpose<<<dim3(8, P2OFF / 128, BB), 256>>>(w, 0);                    // 192 tiles
    k_stage1<<<BB * NPATCH / 2, 128, S1_SMEM>>>(x, g1, b1, m1, v1);

    // Join before stage2 (needs K2) / stage3 (needs W3)
    cudaStreamWaitEvent(0, ev_join, 0);
    k_stage2<<<dim3(BB * 16, HID / 16), 128, S2_SMEM>>>(g2, b2, m2, v2);
    k_stage3<<<BB * NPATCH / 2, 128, S3_SMEM>>>(x, g3, b3, m3, v3, out);
}

// round 17
// speedup vs baseline: 1.0372x; 1.0372x over previous
#include <cuda_runtime.h>
#include <cuda_fp16.h>
#include <cstdint>

#define BB 4
#define CIN 64
#define HH 128
#define WW 128
#define HID 384
#define COUT 64
#define NPATCH 256          // 16 x 16
#define NP 52608            // params per patch
#define P2OFF 24576         // K2 offset (hidden*Cin)
#define P3OFF 28032         // W3 offset (+hidden*9)
#define EPSV 1e-5f

// scratch (static __device__ arrays; no runtime allocation)
__device__ __half g_wth[(size_t)BB * NPATCH * NP];         // fp16 transposed weights ~107MB
__device__ __half g_h1[(size_t)BB * HID * HH * WW];        // image layout, fp16 ~50MB
__device__ __half g_h2[(size_t)BB * NPATCH * HID * 64];    // patch-major [ch][px], fp16 ~50MB

// ---- cp.async helpers
__device__ __forceinline__ void cp16(uint32_t dst_smem, const void* src) {
    asm volatile("cp.async.cg.shared.global [%0], [%1], 16;"
                 :: "r"(dst_smem), "l"(src) : "memory");
}
#define CP_COMMIT() asm volatile("cp.async.commit_group;" ::: "memory")
#define CP_WAIT0()  asm volatile("cp.async.wait_group 0;" ::: "memory")

// ---- mma / ldmatrix helpers (arch-agnostic PTX, works on compute_103)
__device__ __forceinline__ void ldsm4(uint32_t* r, uint32_t addr) {
    asm volatile("ldmatrix.sync.aligned.m8n8.x4.shared.b16 {%0,%1,%2,%3}, [%4];"
                 : "=r"(r[0]), "=r"(r[1]), "=r"(r[2]), "=r"(r[3]) : "r"(addr));
}
__device__ __forceinline__ void ldsm4t(uint32_t* r, uint32_t addr) {
    asm volatile("ldmatrix.sync.aligned.m8n8.x4.trans.shared.b16 {%0,%1,%2,%3}, [%4];"
                 : "=r"(r[0]), "=r"(r[1]), "=r"(r[2]), "=r"(r[3]) : "r"(addr));
}
__device__ __forceinline__ void mma16816(float* d, const uint32_t* a, const uint32_t* b) {
    asm volatile("mma.sync.aligned.m16n8k16.row.col.f32.f16.f16.f32 "
                 "{%0,%1,%2,%3}, {%4,%5,%6,%7}, {%8,%9}, {%0,%1,%2,%3};"
                 : "+f"(d[0]), "+f"(d[1]), "+f"(d[2]), "+f"(d[3])
                 : "r"(a[0]), "r"(a[1]), "r"(a[2]), "r"(a[3]), "r"(b[0]), "r"(b[1]));
}
__device__ __forceinline__ float relu6f(float v) { return fminf(fmaxf(v, 0.f), 6.f); }

// ---------------------------------------------------------------------------
// Transpose w [B][NP][256(fg)] -> g_wth [B][256(fg)][NP]  fp16
// ---------------------------------------------------------------------------
__global__ __launch_bounds__(256) void k_transpose(const float* __restrict__ w) {
    __shared__ float tile[128][33];
    int b = blockIdx.z;
    int g0 = blockIdx.x * 32;
    int p0 = blockIdx.y * 128;
    size_t base = (size_t)b * NP * 256;
    int tid = threadIdx.x;

    #pragma unroll
    for (int t = 0; t < 4; t++) {
        int idx = tid + t * 256;            // 0..1023
        int row = idx >> 3, c4 = (idx & 7) * 4;
        float4 v = *(const float4*)&w[base + (size_t)(p0 + row) * 256 + g0 + c4];
        tile[row][c4]     = v.x;
        tile[row][c4 + 1] = v.y;
        tile[row][c4 + 2] = v.z;
        tile[row][c4 + 3] = v.w;
    }
    __syncthreads();
    #pragma unroll
    for (int t = 0; t < 2; t++) {
        int idx = tid + t * 256;            // 0..511
        int g = idx >> 4, c16 = (idx & 15) * 8;
        __half2 h[4];
        #pragma unroll
        for (int e = 0; e < 4; e++)
            h[e] = __floats2half2_rn(tile[c16 + e * 2][g], tile[c16 + e * 2 + 1][g]);
        uint4 ov = make_uint4(*(uint32_t*)&h[0], *(uint32_t*)&h[1],
                              *(uint32_t*)&h[2], *(uint32_t*)&h[3]);
        *(uint4*)&g_wth[((size_t)b * 256 + g0 + g) * NP + p0 + c16] = ov;
    }
}

// ---------------------------------------------------------------------------
// Stage 1 (HMMA): 2 patches/CTA, 128 threads (4 warps; warp owns 32 px).
// ---------------------------------------------------------------------------
#define HR1 136                          // halves per xs row
#define XS1B (64 * HR1 * 2)              // 17408 bytes
#define RS1 72                           // halves per ws row
#define WS1B (2 * 64 * RS1 * 2)          // 18432 bytes per buffer
__global__ __launch_bounds__(128, 4) void k_stage1(
    const float* __restrict__ x,
    const float* __restrict__ g1, const float* __restrict__ b1,
    const float* __restrict__ m1, const float* __restrict__ v1)
{
    extern __shared__ char sm[];
    uint32_t smem_u32 = (uint32_t)__cvta_generic_to_shared(sm);
    uint32_t xs_u32 = smem_u32;
    uint32_t ws_u32 = smem_u32 + XS1B;

    int blk = blockIdx.x;             // 0..511
    int b = blk >> 7, pp = blk & 127;
    int pid0 = pp * 2, pid1 = pp * 2 + 1;
    int f = pid0 >> 4, gg0 = pid0 & 15;
    int y0 = f * 8, x0 = gg0 * 8;
    int tid = threadIdx.x;
    int warp = tid >> 5, lane = tid & 31;
    int lr = lane & 7, lm = (lane >> 3) & 1, lk = lane >> 4;
    int patch_l = warp >> 1;
    int wb = warp * 32;               // xs column base

    const __half* Wb0 = g_wth + (size_t)(b * NPATCH + pid0) * NP;
    const __half* Wb1 = g_wth + (size_t)(b * NPATCH + pid1) * NP;

    auto fill_ws = [&](int ot, int bsel) {
        #pragma unroll
        for (int t = 0; t < 8; t++) {
            int idx = tid + t * 128;          // 0..1023
            int p = idx >> 9, o = (idx >> 3) & 63, c16 = idx & 7;
            const __half* src = (p ? Wb1 : Wb0) + (ot * 64 + o) * 64 + c16 * 8;
            cp16(ws_u32 + (uint32_t)(bsel * WS1B) +
                 (uint32_t)(p * 64 * RS1 + o * RS1 + c16 * 8) * 2, src);
        }
        CP_COMMIT();
    };

    fill_ws(0, 0);

    // load x (fp32) -> xs fp16 [c][128 px cols]
    for (int idx = tid; idx < 2048; idx += 128) {
        int c = idx >> 5, v = idx & 31;
        int pt = v >> 4, w4 = v & 15;
        int prow = w4 >> 1, q4 = (w4 & 1) * 4;
        float4 xv = *(const float4*)&x[(((size_t)b * CIN + c) * HH + y0 + prow) * WW
                                       + x0 + pt * 8 + q4];
        __half2 h01 = __floats2half2_rn(xv.x, xv.y);
        __half2 h23 = __floats2half2_rn(xv.z, xv.w);
        uint2 pk = make_uint2(*(uint32_t*)&h01, *(uint32_t*)&h23);
        int off = c * HR1 + pt * 64 + prow * 8 + q4;
        *(uint2*)(sm + off * 2) = pk;
    }

    int bb = 0;
    for (int ot = 0; ot < 6; ot++) {
        CP_WAIT0();
        __syncthreads();
        if (ot < 5) fill_ws(ot + 1, bb ^ 1);

        float acc[4][4][4];
        #pragma unroll
        for (int m = 0; m < 4; m++)
            #pragma unroll
            for (int n = 0; n < 4; n++)
                #pragma unroll
                for (int e = 0; e < 4; e++) acc[m][n][e] = 0.f;

        uint32_t wpb = ws_u32 + (uint32_t)(bb * WS1B) + (uint32_t)(patch_l * 64 * RS1) * 2;
        #pragma unroll
        for (int k0 = 0; k0 < 64; k0 += 16) {
            uint32_t a[4][4];
            #pragma unroll
            for (int m = 0; m < 4; m++)
                ldsm4(a[m], wpb + (uint32_t)((m * 16 + lr + lm * 8) * RS1 + k0 + lk * 8) * 2);
            uint32_t bf[2][4];
            #pragma unroll
            for (int h = 0; h < 2; h++)
                ldsm4t(bf[h], xs_u32 + (uint32_t)((k0 + lr + lm * 8) * HR1 + wb + h * 16 + lk * 8) * 2);
            #pragma unroll
            for (int m = 0; m < 4; m++)
                #pragma unroll
                for (int n = 0; n < 4; n++)
                    mma16816(acc[m][n], a[m], &bf[n >> 1][(n & 1) * 2]);
        }

        // epilogue: bn1 + relu6 -> fp16 h1
        int q = (lane & 3) * 2;
        #pragma unroll
        for (int m = 0; m < 4; m++) {
            int o0 = ot * 64 + m * 16 + (lane >> 2);
            int o1 = o0 + 8;
            float inv0 = g1[o0] * rsqrtf(v1[o0] + EPSV);
            float sh0  = b1[o0] - m1[o0] * inv0;
            float inv1 = g1[o1] * rsqrtf(v1[o1] + EPSV);
            float sh1  = b1[o1] - m1[o1] * inv1;
            #pragma unroll
            for (int n = 0; n < 4; n++) {
                int p = (warp & 1) * 4 + n;
                size_t col = (size_t)x0 + patch_l * 8 + q;
                __half2 v0 = __floats2half2_rn(relu6f(acc[m][n][0] * inv0 + sh0),
                                               relu6f(acc[m][n][1] * inv0 + sh0));
                __half2 v1h = __floats2half2_rn(relu6f(acc[m][n][2] * inv1 + sh1),
                                                relu6f(acc[m][n][3] * inv1 + sh1));
                *(__half2*)&g_h1[(((size_t)b * HID + o0) * HH + y0 + p) * WW + col] = v0;
                *(__half2*)&g_h1[(((size_t)b * HID + o1) * HH + y0 + p) * WW + col] = v1h;
            }
        }
        bb ^= 1;
    }
}

// ---------------------------------------------------------------------------
// Stage 2 (vectorized rows, high-occupancy): CTA = (b, f-row, 8-ch group).
// 128 threads = (cl in 8, p in 8, s in 2); each thread slides an 8-px window
// across 8 patches. smem 24.3KB -> 6 CTAs/SM.
// ---------------------------------------------------------------------------
#define S2_HROW 136                         // halves per hs row
#define S2_HSB  (8 * 10 * S2_HROW * 2)      // 21760 bytes
#define S2_KSB  (16 * 80 * 2)               // 2560 bytes
#define S2_SMEM (S2_HSB + S2_KSB)           // 24320 bytes
__global__ __launch_bounds__(128, 6) void k_stage2(
    const float* __restrict__ g2, const float* __restrict__ b2,
    const float* __restrict__ m2, const float* __restrict__ v2)
{
    extern __shared__ char sm2[];
    __half* hs = (__half*)sm2;              // [8 cl][10 ry][136]
    __half* ks = (__half*)(sm2 + S2_HSB);   // [16 patch][80]
    int bf = blockIdx.x;                    // b*16 + f
    int b = bf >> 4, f = bf & 15;
    int ch0 = blockIdx.y * 8;
    int tid = threadIdx.x;
    int y0 = f * 8;

    // fill hs: 8ch x 10 rows x 16 uint4 = 1280
    for (int idx = tid; idx < 1280; idx += 128) {
        int cl = idx / 160;
        int rem = idx - cl * 160;
        int ry = rem >> 4, c16 = rem & 15;
        int yy = y0 + ry - 1;
        yy = yy < 0 ? -yy : (yy >= HH ? 2 * HH - 2 - yy : yy);
        uint4 raw = *(const uint4*)&g_h1[(((size_t)b * HID + ch0 + cl) * HH + yy) * WW + c16 * 8];
        *(uint4*)&hs[cl * 1360 + ry * S2_HROW + c16 * 8] = raw;
    }
    // fill ks: 16 patches x 9 uint4 (72 contiguous halves per patch)
    for (int idx = tid; idx < 144; idx += 128) {
        int g = idx / 9, u = idx - (idx / 9) * 9;
        const __half* src = g_wth + (size_t)(b * NPATCH + f * 16 + g) * NP
                            + P2OFF + ch0 * 9 + u * 8;
        *(uint4*)&ks[g * 80 + u * 8] = *(const uint4*)src;
    }
    __syncthreads();

    int cl = tid >> 4;
    int rem = tid & 15;
    int p = rem & 7, s = rem >> 3;
    int ch = ch0 + cl;
    float inv = g2[ch] * rsqrtf(v2[ch] + EPSV);
    float sh  = b2[ch] - m2[ch] * inv;
    const __half* hrow = hs + cl * 1360 + p * S2_HROW;   // rows p, p+1, p+2
    int cbase = s * 64;

    float cur[3][8], nxt[3][8], pl[3];
    #pragma unroll
    for (int r = 0; r < 3; r++) {
        uint4 raw = *(const uint4*)(hrow + r * S2_HROW + cbase);
        __half2* hp = (__half2*)&raw;
        #pragma unroll
        for (int e = 0; e < 4; e++) {
            float2 fv = __half22float2(hp[e]);
            cur[r][e * 2] = fv.x; cur[r][e * 2 + 1] = fv.y;
        }
    }
    #pragma unroll
    for (int r = 0; r < 3; r++)
        pl[r] = s ? __half2float(hrow[r * S2_HROW + 63]) : cur[r][1];

    for (int gl = 0; gl < 8; gl++) {
        float nx0[3];
        if (gl < 7) {
            #pragma unroll
            for (int r = 0; r < 3; r++) {
                uint4 raw = *(const uint4*)(hrow + r * S2_HROW + cbase + (gl + 1) * 8);
                __half2* hp = (__half2*)&raw;
                #pragma unroll
                for (int e = 0; e < 4; e++) {
                    float2 fv = __half22float2(hp[e]);
                    nxt[r][e * 2] = fv.x; nxt[r][e * 2 + 1] = fv.y;
                }
            }
            #pragma unroll
            for (int r = 0; r < 3; r++) nx0[r] = nxt[r][0];
        } else if (s == 0) {
            #pragma unroll
            for (int r = 0; r < 3; r++) nx0[r] = __half2float(hrow[r * S2_HROW + 64]);
        } else {
            #pragma unroll
            for (int r = 0; r < 3; r++) nx0[r] = cur[r][6];   // reflect right edge
        }

        int g = s * 8 + gl;
        float kv[9];
        #pragma unroll
        for (int t = 0; t < 9; t++)
            kv[t] = __half2float(ks[g * 80 + cl * 9 + t]);

        float res[8];
        #pragma unroll
        for (int q = 0; q < 8; q++) {
            float a = 0.f;
            #pragma unroll
            for (int r = 0; r < 3; r++) {
                float wl = (q == 0) ? pl[r] : cur[r][q - 1];
                float wc = cur[r][q];
                float wr = (q == 7) ? nx0[r] : cur[r][q + 1];
                a += wl * kv[r * 3] + wc * kv[r * 3 + 1] + wr * kv[r * 3 + 2];
            }
            res[q] = relu6f(a * inv + sh);
        }

        __half2 q0 = __floats2half2_rn(res[0], res[1]);
        __half2 q1 = __floats2half2_rn(res[2], res[3]);
        __half2 q2 = __floats2half2_rn(res[4], res[5]);
        __half2 q3 = __floats2half2_rn(res[6], res[7]);
        uint4 ov = make_uint4(*(uint32_t*)&q0, *(uint32_t*)&q1,
                              *(uint32_t*)&q2, *(uint32_t*)&q3);
        int pid = f * 16 + g;
        *(uint4*)&g_h2[((size_t)(b * NPATCH + pid) * HID + ch) * 64 + p * 8] = ov;

        if (gl < 7) {
            #pragma unroll
            for (int r = 0; r < 3; r++) {
                pl[r] = cur[r][7];
                #pragma unroll
                for (int e = 0; e < 8; e++) cur[r][e] = nxt[r][e];
            }
        }
    }
}

// ---------------------------------------------------------------------------
// Stage 3 (HMMA): 2 patches/CTA, K=384 in chunks of 32, cp.async dbl-buffered.
// ---------------------------------------------------------------------------
#define HR3 136                            // halves per hs row
#define HS3B (32 * HR3 * 2)                // 8704 bytes
#define RS3 40                             // halves per ws row
#define WS3B (2 * 64 * RS3 * 2)            // 10240 bytes
#define BUF3 (HS3B + WS3B)                 // 18944 bytes per buffer
__global__ __launch_bounds__(128, 4) void k_stage3(
    const float* __restrict__ x,
    const float* __restrict__ g3, const float* __restrict__ b3,
    const float* __restrict__ m3, const float* __restrict__ v3,
    float* __restrict__ out)
{
    extern __shared__ char sm[];
    uint32_t smem_u32 = (uint32_t)__cvta_generic_to_shared(sm);

    int blk = blockIdx.x;             // 0..511
    int b = blk >> 7, pp = blk & 127;
    int pid0 = pp * 2, pid1 = pp * 2 + 1;
    int f = pid0 >> 4, gg0 = pid0 & 15;
    int y0 = f * 8, x0 = gg0 * 8;
    int tid = threadIdx.x;
    int warp = tid >> 5, lane = tid & 31;
    int lr = lane & 7, lm = (lane >> 3) & 1, lk = lane >> 4;
    int patch_l = warp >> 1;
    int wb = warp * 32;

    const __half* Wb0 = g_wth + (size_t)(b * NPATCH + pid0) * NP + P3OFF;
    const __half* Wb1 = g_wth + (size_t)(b * NPATCH + pid1) * NP + P3OFF;
    const __half* Hb0 = g_h2 + (size_t)(b * NPATCH + pid0) * HID * 64;
    const __half* Hb1 = g_h2 + (size_t)(b * NPATCH + pid1) * HID * 64;

    auto fill3 = [&](int kt, int bsel) {
        uint32_t base = smem_u32 + (uint32_t)(bsel * BUF3);
        #pragma unroll
        for (int t = 0; t < 4; t++) {           // hs: 32k x 128px
            int idx = tid + t * 128;
            int k = idx >> 4, rem = idx & 15;
            int pt = rem >> 3, w8 = rem & 7;
            const __half* src = (pt ? Hb1 : Hb0) + (kt * 32 + k) * 64 + w8 * 8;
            cp16(base + (uint32_t)(k * HR3 + pt * 64 + w8 * 8) * 2, src);
        }
        #pragma unroll
        for (int t = 0; t < 4; t++) {           // ws: 2p x 64co x 32k
            int idx = tid + t * 128;
            int p = idx >> 8, rem = idx & 255;
            int co = rem >> 2, c16 = rem & 3;
            const __half* src = (p ? Wb1 : Wb0) + co * HID + kt * 32 + c16 * 8;
            cp16(base + HS3B + (uint32_t)(p * 64 * RS3 + co * RS3 + c16 * 8) * 2, src);
        }
        CP_COMMIT();
    };

    fill3(0, 0);

    float acc[4][4][4];
    #pragma unroll
    for (int m = 0; m < 4; m++)
        #pragma unroll
        for (int n = 0; n < 4; n++)
            #pragma unroll
            for (int e = 0; e < 4; e++) acc[m][n][e] = 0.f;

    int bb = 0;
    for (int kt = 0; kt < 12; kt++) {
        CP_WAIT0();
        __syncthreads();
        if (kt < 11) fill3(kt + 1, bb ^ 1);

        uint32_t hsb = smem_u32 + (uint32_t)(bb * BUF3);
        uint32_t wpb = hsb + HS3B + (uint32_t)(patch_l * 64 * RS3) * 2;
        #pragma unroll
        for (int k0 = 0; k0 < 32; k0 += 16) {
            uint32_t a[4][4];
            #pragma unroll
            for (int m = 0; m < 4; m++)
                ldsm4(a[m], wpb + (uint32_t)((m * 16 + lr + lm * 8) * RS3 + k0 + lk * 8) * 2);
            uint32_t bf[2][4];
            #pragma unroll
            for (int h = 0; h < 2; h++)
                ldsm4t(bf[h], hsb + (uint32_t)((k0 + lr + lm * 8) * HR3 + wb + h * 16 + lk * 8) * 2);
            #pragma unroll
            for (int m = 0; m < 4; m++)
                #pragma unroll
                for (int n = 0; n < 4; n++)
                    mma16816(acc[m][n], a[m], &bf[n >> 1][(n & 1) * 2]);
        }
        bb ^= 1;
    }

    // epilogue: out = x + bn3(acc)
    int q = (lane & 3) * 2;
    #pragma unroll
    for (int m = 0; m < 4; m++) {
        int co0 = m * 16 + (lane >> 2);
        int co1 = co0 + 8;
        float inv0 = g3[co0] * rsqrtf(v3[co0] + EPSV);
        float sh0  = b3[co0] - m3[co0] * inv0;
        float inv1 = g3[co1] * rsqrtf(v3[co1] + EPSV);
        float sh1  = b3[co1] - m3[co1] * inv1;
        #pragma unroll
        for (int n = 0; n < 4; n++) {
            int p = (warp & 1) * 4 + n;
            size_t col = (size_t)x0 + patch_l * 8 + q;
            size_t a0 = (((size_t)b * COUT + co0) * HH + y0 + p) * WW + col;
            size_t a1 = (((size_t)b * COUT + co1) * HH + y0 + p) * WW + col;
            float2 xr0 = *(const float2*)&x[a0];
            float2 xr1 = *(const float2*)&x[a1];
            float2 o0 = make_float2(xr0.x + (acc[m][n][0] * inv0 + sh0),
                                    xr0.y + (acc[m][n][1] * inv0 + sh0));
            float2 o1 = make_float2(xr1.x + (acc[m][n][2] * inv1 + sh1),
                                    xr1.y + (acc[m][n][3] * inv1 + sh1));
            *(float2*)&out[a0] = o0;
            *(float2*)&out[a1] = o1;
        }
    }
}

// ---------------------------------------------------------------------------
extern "C" void kernel_launch(void* const* d_in, const int* in_sizes, int n_in,
                              void* d_out, int out_size) {
    const float* x  = (const float*)d_in[0];
    const float* w  = (const float*)d_in[1];
    const float* g1 = (const float*)d_in[2];
    const float* b1 = (const float*)d_in[3];
    const float* m1 = (const float*)d_in[4];
    const float* v1 = (const float*)d_in[5];
    const float* g2 = (const float*)d_in[6];
    const float* b2 = (const float*)d_in[7];
    const float* m2 = (const float*)d_in[8];
    const float* v2 = (const float*)d_in[9];
    const float* g3 = (const float*)d_in[10];
    const float* b3 = (const float*)d_in[11];
    const float* m3 = (const float*)d_in[12];
    const float* v3 = (const float*)d_in[13];
    float* out = (float*)d_out;

    const int S1_SMEM = XS1B + 2 * WS1B;   // 54272
    const int S3_SMEM = 2 * BUF3;          // 37888
    cudaFuncSetAttribute(k_stage1, cudaFuncAttributeMaxDynamicSharedMemorySize, S1_SMEM);
    cudaFuncSetAttribute(k_stage2, cudaFuncAttributeMaxDynamicSharedMemorySize, S2_SMEM);
    cudaFuncSetAttribute(k_stage3, cudaFuncAttributeMaxDynamicSharedMemorySize, S3_SMEM);

    k_transpose<<<dim3(8, NP / 128, BB), 256>>>(w);
    k_stage1<<<BB * NPATCH / 2, 128, S1_SMEM>>>(x, g1, b1, m1, v1);
    k_stage2<<<dim3(BB * 16, HID / 8), 128, S2_SMEM>>>(g2, b2, m2, v2);
    k_stage3<<<BB * NPATCH / 2, 128, S3_SMEM>>>(x, g3, b3, m3, v3, out);
}